// round 1
// baseline (speedup 1.0000x reference)
#include <cuda_runtime.h>
#include <math.h>

#define S_LEN   2048
#define D_DIM   64
#define BH      32
#define BM      128        // query rows per CTA (1 per thread)
#define BN      32         // key tile
#define NTILES  (S_LEN / BN)
#define THREADS 128

typedef unsigned long long u64;

// ---- packed f32x2 helpers (sm_103a) ----
__device__ __forceinline__ u64 pack2(float lo, float hi) {
    u64 r; asm("mov.b64 %0, {%1,%2};" : "=l"(r) : "f"(lo), "f"(hi)); return r;
}
__device__ __forceinline__ void unpack2(u64 v, float& a, float& b) {
    asm("mov.b64 {%0,%1}, %2;" : "=f"(a), "=f"(b) : "l"(v));
}
__device__ __forceinline__ u64 ffma2(u64 a, u64 b, u64 c) {
    u64 d; asm("fma.rn.f32x2 %0, %1, %2, %3;" : "=l"(d) : "l"(a), "l"(b), "l"(c)); return d;
}
__device__ __forceinline__ u64 fmul2(u64 a, u64 b) {
    u64 d; asm("mul.rn.f32x2 %0, %1, %2;" : "=l"(d) : "l"(a), "l"(b)); return d;
}
__device__ __forceinline__ u64 fadd2(u64 a, u64 b) {
    u64 d; asm("add.rn.f32x2 %0, %1, %2;" : "=l"(d) : "l"(a), "l"(b)); return d;
}
__device__ __forceinline__ float ex2f(float x) {
    float r; asm("ex2.approx.f32 %0, %1;" : "=f"(r) : "f"(x)); return r;
}

__global__ void __launch_bounds__(THREADS, 2)
SimpleAttentionModel_39943195853086_kernel(
    const float* __restrict__ Q, const float* __restrict__ K,
    const float* __restrict__ V, const float* __restrict__ dsq,
    float* __restrict__ Out)
{
    __shared__ __align__(16) float Ks[BN * D_DIM];
    __shared__ __align__(16) float Vs[BN * D_DIM];

    const int tid = threadIdx.x;
    const int bh  = blockIdx.y;
    const long hbase = (long)bh * S_LEN * D_DIM;
    const int row = blockIdx.x * BM + tid;

    // base-2 softmax: fold log2(e)/sqrt(D) into q
    const float scale = 1.4426950408889634f / dsq[0];
    const u64 scale2 = pack2(scale, scale);

    // q row in registers as 32 packed pairs (64 floats)
    u64 q[32];
    {
        const ulonglong2* qg = (const ulonglong2*)(Q + hbase + (long)row * D_DIM);
        #pragma unroll
        for (int i = 0; i < 16; i++) {
            ulonglong2 v = qg[i];
            q[2*i]   = fmul2(v.x, scale2);
            q[2*i+1] = fmul2(v.y, scale2);
        }
    }

    // O accumulator: 32 pairs (64 floats)
    u64 o[32];
    #pragma unroll
    for (int i = 0; i < 32; i++) o[i] = 0ull;

    float m = -1e30f;
    float l = 0.0f;

    for (int t = 0; t < NTILES; t++) {
        __syncthreads();   // previous tile's PV reads done before overwrite
        // ---- stage K/V tile (row-major, coalesced, conflict-free) ----
        {
            const float4* kg = (const float4*)(K + hbase + (long)t * BN * D_DIM);
            const float4* vg = (const float4*)(V + hbase + (long)t * BN * D_DIM);
            float4* ks4 = (float4*)Ks;
            float4* vs4 = (float4*)Vs;
            #pragma unroll
            for (int i = 0; i < 4; i++) {
                ks4[tid + i * THREADS] = kg[tid + i * THREADS];
                vs4[tid + i * THREADS] = vg[tid + i * THREADS];
            }
        }
        __syncthreads();

        // ---- S = q . K^T  (packed along d; both operands contiguous) ----
        float s[BN];
        #pragma unroll
        for (int kk = 0; kk < BN; kk++) {
            const ulonglong2* kr = (const ulonglong2*)(Ks + kk * D_DIM);
            u64 a0 = 0ull, a1 = 0ull, a2 = 0ull, a3 = 0ull;
            #pragma unroll
            for (int i = 0; i < 8; i++) {
                ulonglong2 kv0 = kr[2*i];
                ulonglong2 kv1 = kr[2*i + 1];
                a0 = ffma2(q[4*i + 0], kv0.x, a0);
                a1 = ffma2(q[4*i + 1], kv0.y, a1);
                a2 = ffma2(q[4*i + 2], kv1.x, a2);
                a3 = ffma2(q[4*i + 3], kv1.y, a3);
            }
            u64 ab = fadd2(fadd2(a0, a1), fadd2(a2, a3));
            float xa, xb; unpack2(ab, xa, xb);
            s[kk] = xa + xb;
        }

        // ---- thread-local online softmax ----
        float tm0 = s[0], tm1 = s[1], tm2 = s[2], tm3 = s[3];
        #pragma unroll
        for (int kk = 4; kk < BN; kk += 4) {
            tm0 = fmaxf(tm0, s[kk]);
            tm1 = fmaxf(tm1, s[kk+1]);
            tm2 = fmaxf(tm2, s[kk+2]);
            tm3 = fmaxf(tm3, s[kk+3]);
        }
        float tmax = fmaxf(fmaxf(tm0, tm1), fmaxf(tm2, tm3));
        float mn = fmaxf(m, tmax);
        float alpha = ex2f(m - mn);    // m=-1e30 first tile -> alpha=0
        m = mn;

        u64 al2 = pack2(alpha, alpha);
        #pragma unroll
        for (int i = 0; i < 32; i++) o[i] = fmul2(o[i], al2);

        float p[BN];
        float ls0 = 0.f, ls1 = 0.f, ls2 = 0.f, ls3 = 0.f;
        #pragma unroll
        for (int kk = 0; kk < BN; kk += 4) {
            p[kk]   = ex2f(s[kk]   - mn); ls0 += p[kk];
            p[kk+1] = ex2f(s[kk+1] - mn); ls1 += p[kk+1];
            p[kk+2] = ex2f(s[kk+2] - mn); ls2 += p[kk+2];
            p[kk+3] = ex2f(s[kk+3] - mn); ls3 += p[kk+3];
        }
        l = l * alpha + ((ls0 + ls1) + (ls2 + ls3));

        // ---- O += P @ V  (broadcast p, contiguous V pairs) ----
        #pragma unroll
        for (int kk = 0; kk < BN; kk++) {
            u64 pp = pack2(p[kk], p[kk]);
            const ulonglong2* vr = (const ulonglong2*)(Vs + kk * D_DIM);
            #pragma unroll
            for (int i = 0; i < 8; i++) {
                ulonglong2 vv0 = vr[2*i];
                ulonglong2 vv1 = vr[2*i + 1];
                o[4*i + 0] = ffma2(pp, vv0.x, o[4*i + 0]);
                o[4*i + 1] = ffma2(pp, vv0.y, o[4*i + 1]);
                o[4*i + 2] = ffma2(pp, vv1.x, o[4*i + 2]);
                o[4*i + 3] = ffma2(pp, vv1.y, o[4*i + 3]);
            }
        }
    }

    // ---- epilogue: normalize and store row ----
    float invl = 1.0f / l;
    u64 il2 = pack2(invl, invl);
    float4* og = (float4*)(Out + hbase + (long)row * D_DIM);
    #pragma unroll
    for (int i = 0; i < 16; i++) {
        float a, b, c, d;
        unpack2(fmul2(o[2*i],     il2), a, b);
        unpack2(fmul2(o[2*i + 1], il2), c, d);
        og[i] = make_float4(a, b, c, d);
    }
}

extern "C" void kernel_launch(void* const* d_in, const int* in_sizes, int n_in,
                              void* d_out, int out_size) {
    const float* Q  = (const float*)d_in[0];
    const float* K  = (const float*)d_in[1];
    const float* V  = (const float*)d_in[2];
    const float* ds = (const float*)d_in[3];
    float* Out = (float*)d_out;

    dim3 grid(S_LEN / BM, BH);
    SimpleAttentionModel_39943195853086_kernel<<<grid, THREADS>>>(Q, K, V, ds, Out);
}